// round 12
// baseline (speedup 1.0000x reference)
#include <cuda_runtime.h>
#include <cuda_bf16.h>
#include <cstdint>

// ---------------- Problem dims ----------------
#define M_REAL 200              // T*C rows
#define M_PAD 256               // padded to 16 m16 tiles (hi limb only)
#define KK 16384                // H*W
#define NN 8192                 // D
#define DTILE 64                // d columns per CTA
#define KCH 64                  // k per chunk
#define NCH (KK / KCH)          // 256 chunks
#define NDT (NN / DTILE)        // 128 CTAs
#define THRESH 12.0f

#define ABYTES (M_PAD * 128)    // 32768 per chunk (hi bf16, swizzled)
#define NSTAGE 4

// gemm smem layout
#define SM_A 0                               // 4 x 32768 = 131072
#define SM_BT (NSTAGE * ABYTES)              // B bf16 tile: 64 x 144 = 9216
#define SM_BITS (SM_BT + 9216)               // bits double buffer: 2 x 512
#define SM_MBAR (SM_BITS + 1024)             // 4 mbars
#define SM_SG (SM_MBAR + 32)                 // 64 floats
#define SMEM_TOTAL (SM_SG + 256)             // 141600

// ---------------- device scratch (static, no runtime allocation) ----------------
__device__ __nv_bfloat16 g_A[NCH * M_PAD * 64];   // 8 MB hi-limb, chunk-tiled+swizzled
__device__ __nv_bfloat16 g_Alo[M_REAL * KK];      // 6.5 MB lo-limb, flat
__device__ uint32_t g_Bbits[NCH * NDT * 128];     // 16 MB bit-packed pos_w signs
__device__ float g_score[NN];

// ---------------- PTX helpers ----------------
#define MBAR_INIT(a, c) asm volatile("mbarrier.init.shared.b64 [%0], %1;" :: "r"(a), "r"(c) : "memory")
#define MBAR_EXPECT(a, n) asm volatile("mbarrier.arrive.expect_tx.shared.b64 _, [%0], %1;" :: "r"(a), "r"(n) : "memory")

static __device__ __forceinline__ void mbar_wait(uint32_t mbar, uint32_t parity) {
    asm volatile(
        "{\n\t.reg .pred P1;\n\t"
        "WAIT_LOOP_%=:\n\t"
        "mbarrier.try_wait.parity.acquire.cta.shared::cta.b64 P1, [%0], %1, 0x989680;\n\t"
        "@P1 bra.uni WAIT_DONE_%=;\n\t"
        "bra.uni WAIT_LOOP_%=;\n\t"
        "WAIT_DONE_%=:\n\t}"
        :: "r"(mbar), "r"(parity) : "memory");
}

static __device__ __forceinline__ void bulk_g2s(uint32_t dst, const void* src,
                                                uint32_t bytes, uint32_t mbar) {
    asm volatile(
        "cp.async.bulk.shared::cluster.global.mbarrier::complete_tx::bytes [%0], [%1], %2, [%3];"
        :: "r"(dst), "l"(src), "r"(bytes), "r"(mbar) : "memory");
}

static __device__ __forceinline__ void ldsm_x4(uint32_t* r, uint32_t addr) {
    asm volatile("ldmatrix.sync.aligned.m8n8.x4.shared.b16 {%0,%1,%2,%3}, [%4];"
                 : "=r"(r[0]), "=r"(r[1]), "=r"(r[2]), "=r"(r[3]) : "r"(addr));
}
static __device__ __forceinline__ void ldsm_x2t(uint32_t* r, uint32_t addr) {
    asm volatile("ldmatrix.sync.aligned.m8n8.x2.trans.shared.b16 {%0,%1}, [%2];"
                 : "=r"(r[0]), "=r"(r[1]) : "r"(addr));
}
static __device__ __forceinline__ void mma_bf16(float* c, const uint32_t* a, const uint32_t* b) {
    asm volatile(
        "mma.sync.aligned.m16n8k16.row.col.f32.bf16.bf16.f32 "
        "{%0,%1,%2,%3}, {%4,%5,%6,%7}, {%8,%9}, {%0,%1,%2,%3};"
        : "+f"(c[0]), "+f"(c[1]), "+f"(c[2]), "+f"(c[3])
        : "r"(a[0]), "r"(a[1]), "r"(a[2]), "r"(a[3]), "r"(b[0]), "r"(b[1]));
}

// ---------------- kernel 1: hist -> hi bf16 (chunk-tiled, swizzled) + lo bf16 (flat) ----------------
__global__ void convA(const float* __restrict__ hist) {
    int idx = blockIdx.x * blockDim.x + threadIdx.x;   // 256 m x 2048 units
    int m = idx >> 11;
    int u = idx & 2047;
    int kc = u >> 3, uu = u & 7;
    __nv_bfloat16 hi[8], lo[8];
    if (m < M_REAL) {
        const float* src = hist + (size_t)m * KK + u * 8;
        float4 f0 = *(const float4*)(src);
        float4 f1 = *(const float4*)(src + 4);
        float f[8] = {f0.x, f0.y, f0.z, f0.w, f1.x, f1.y, f1.z, f1.w};
        #pragma unroll
        for (int i = 0; i < 8; i++) {
            hi[i] = __float2bfloat16_rn(f[i]);
            lo[i] = __float2bfloat16_rn(f[i] - __bfloat162float(hi[i]));
        }
    } else {
        #pragma unroll
        for (int i = 0; i < 8; i++) hi[i] = __float2bfloat16_rn(0.f);
    }
    int sw = (uu ^ (m & 7)) * 16;
    *(uint4*)((char*)g_A + (size_t)kc * ABYTES + m * 128 + sw) = *(uint4*)hi;
    if (m < M_REAL)
        *(uint4*)(g_Alo + (size_t)m * KK + u * 8) = *(uint4*)lo;
}

// ---------------- kernel 2: pos_w -> bit-packed signs, (chunk,dtile)-tiled ----------------
// one CTA per k-chunk; smem transpose for coalesced writes
#define CB_SMEM (64 * 257 * 4)   // 65792
__global__ void __launch_bounds__(256)
convB2(const float* __restrict__ pos_w) {
    extern __shared__ uint32_t bsm[];   // [64][257]
    const int tid = threadIdx.x;
    const int kc = blockIdx.x;

    // phase 1: each row k, 256 threads x 32 floats -> sign words
    for (int r = 0; r < 64; r++) {
        const float* src = pos_w + (size_t)(kc * 64 + r) * NN + tid * 32;
        uint32_t bits = 0;
        #pragma unroll
        for (int i = 0; i < 8; i++) {
            float4 f = *(const float4*)(src + i * 4);
            bits |= (__float_as_uint(f.x) >> 31) << (i * 4 + 0);
            bits |= (__float_as_uint(f.y) >> 31) << (i * 4 + 1);
            bits |= (__float_as_uint(f.z) >> 31) << (i * 4 + 2);
            bits |= (__float_as_uint(f.w) >> 31) << (i * 4 + 3);
        }
        bsm[r * 257 + tid] = bits;
    }
    __syncthreads();

    // phase 2: write [dt 128][k 64][2 words] coalesced
    uint32_t* outp = g_Bbits + (size_t)kc * NDT * 128;
    #pragma unroll
    for (int it = 0; it < 64; it++) {
        int u = tid + it * 256;          // 0..16383
        int h = u & 1, k = (u >> 1) & 63, dt = u >> 7;
        outp[u] = bsm[k * 257 + dt * 2 + h];
    }
}

// ---------------- kernel 3: hi bf16 GEMM, fat-bulk A + bit-expanded B ----------------
__global__ void __launch_bounds__(256)
st_gemm(const float* __restrict__ time_w,
        const float* __restrict__ pol_w)
{
    extern __shared__ char smem[];
    const uint32_t sbase = (uint32_t)__cvta_generic_to_shared(smem);
    const int tid = threadIdx.x;
    const int w = tid >> 5, lane = tid & 31;
    const int g = lane >> 2, t = lane & 3;
    const int wm = w & 3, wn = w >> 2;      // 4m x 2n warp grid
    const int dt = blockIdx.x;
    const int d0 = dt * DTILE;
    float* sg = (float*)(smem + SM_SG);
    uint32_t* bitsm = (uint32_t*)(smem + SM_BITS);

    if (tid < NSTAGE) MBAR_INIT(sbase + SM_MBAR + tid * 8, 1);
    if (tid < 64) sg[tid] = 0.0f;
    __syncthreads();

    // prologue: bits for chunks 0,1 via LDG; A bulks for stages 0..3
    if (tid < 64) {
        int cb = tid >> 5;               // chunk 0 or 1
        int l = tid & 31;
        uint4 v = *(const uint4*)(g_Bbits + ((size_t)cb * NDT + dt) * 128 + l * 4);
        *(uint4*)(bitsm + cb * 128 + l * 4) = v;
    }
    if (tid == 0) {
        #pragma unroll
        for (int s = 0; s < NSTAGE; s++) {
            uint32_t mb = sbase + SM_MBAR + s * 8;
            MBAR_EXPECT(mb, ABYTES);
            bulk_g2s(sbase + s * ABYTES, (const char*)g_A + (size_t)s * ABYTES, ABYTES, mb);
        }
    }
    __syncthreads();

    float acc[4][4][4];
    #pragma unroll
    for (int i = 0; i < 4; i++)
        #pragma unroll
        for (int j = 0; j < 4; j++)
            #pragma unroll
            for (int cc = 0; cc < 4; cc++) acc[i][j][cc] = 0.0f;

    const int Lr = lane & 15;
    const int arow_l = (lane & 7) + ((lane >> 3) & 1) * 8;
    const int asel = lane >> 4;
    const int ek = tid & 63, eh = tid >> 6;     // expansion mapping

    for (int c = 0; c < NCH; c++) {
        const int s = c & 3;
        mbar_wait(sbase + SM_MBAR + s * 8, (uint32_t)((c >> 2) & 1));

        // expand 16 bits -> 16 bf16 (8 words) into B tile (pitch 144)
        {
            uint32_t wv = bitsm[(c & 1) * 128 + ek * 2 + (eh >> 1)];
            uint32_t bits = (wv >> ((eh & 1) * 16)) & 0xFFFFu;
            uint32_t e[8];
            #pragma unroll
            for (int j = 0; j < 8; j++) {
                e[j] = 0x3F803F80u | (((bits >> (2 * j)) & 1u) << 15)
                                   | (((bits >> (2 * j + 1)) & 1u) << 31);
            }
            char* dst = smem + SM_BT + ek * 144 + eh * 32;
            *(uint4*)(dst) = make_uint4(e[0], e[1], e[2], e[3]);
            *(uint4*)(dst + 16) = make_uint4(e[4], e[5], e[6], e[7]);
        }
        __syncthreads();

        // compute
        {
            const uint32_t stA = sbase + (uint32_t)s * ABYTES;
            const uint32_t stB = sbase + SM_BT;
            #pragma unroll
            for (int kt = 0; kt < 4; kt++) {
                uint32_t bfr[4][2];
                #pragma unroll
                for (int j = 0; j < 4; j++) {
                    int nf = wn * 4 + j;
                    int k = kt * 16 + Lr;
                    ldsm_x2t(bfr[j], stB + (uint32_t)(k * 144 + nf * 16));
                }
                #pragma unroll
                for (int i = 0; i < 4; i++) {
                    int r = (wm + 4 * i) * 16 + arow_l;
                    int u = kt * 2 + asel;
                    uint32_t a[4];
                    ldsm_x4(a, stA + (uint32_t)(r * 128 + ((u ^ (r & 7)) << 4)));
                    #pragma unroll
                    for (int j = 0; j < 4; j++)
                        mma_bf16(acc[i][j], a, bfr[j]);
                }
            }
        }
        __syncthreads();

        if (c + NSTAGE < NCH && tid == 0) {
            uint32_t mb = sbase + SM_MBAR + s * 8;
            MBAR_EXPECT(mb, ABYTES);
            bulk_g2s(sbase + s * ABYTES,
                     (const char*)g_A + (size_t)(c + NSTAGE) * ABYTES, ABYTES, mb);
        }
        if (c + 2 < NCH && tid < 32) {
            uint4 v = *(const uint4*)(g_Bbits + ((size_t)(c + 2) * NDT + dt) * 128 + tid * 4);
            *(uint4*)(bitsm + (c & 1) * 128 + tid * 4) = v;
        }
    }

    // ---- epilogue: score[d] = sum_m C[m,d]*time*pol (hi limb only) ----
    {
        float colsum[4][2];
        #pragma unroll
        for (int j = 0; j < 4; j++) { colsum[j][0] = 0.f; colsum[j][1] = 0.f; }
        #pragma unroll
        for (int i = 0; i < 4; i++) {
            int rg = (wm + 4 * i) * 16 + g;
            int m0 = rg, m1 = rg + 8;
            bool v0 = m0 < M_REAL, v1 = m1 < M_REAL;
            #pragma unroll
            for (int j = 0; j < 4; j++) {
                int d = d0 + (wn * 4 + j) * 8 + 2 * t;
                if (v0) {
                    float wa = time_w[(size_t)(m0 >> 1) * NN + d] * pol_w[(size_t)(m0 & 1) * NN + d];
                    float wb = time_w[(size_t)(m0 >> 1) * NN + d + 1] * pol_w[(size_t)(m0 & 1) * NN + d + 1];
                    colsum[j][0] += acc[i][j][0] * wa;
                    colsum[j][1] += acc[i][j][1] * wb;
                }
                if (v1) {
                    float wa = time_w[(size_t)(m1 >> 1) * NN + d] * pol_w[(size_t)(m1 & 1) * NN + d];
                    float wb = time_w[(size_t)(m1 >> 1) * NN + d + 1] * pol_w[(size_t)(m1 & 1) * NN + d + 1];
                    colsum[j][0] += acc[i][j][2] * wa;
                    colsum[j][1] += acc[i][j][3] * wb;
                }
            }
        }
        #pragma unroll
        for (int j = 0; j < 4; j++) {
            #pragma unroll
            for (int cx = 0; cx < 2; cx++) {
                float v = colsum[j][cx];
                v += __shfl_xor_sync(0xFFFFFFFFu, v, 4);
                v += __shfl_xor_sync(0xFFFFFFFFu, v, 8);
                v += __shfl_xor_sync(0xFFFFFFFFu, v, 16);
                if (g == 0)
                    atomicAdd(&sg[(wn * 4 + j) * 8 + 2 * t + cx], v);
            }
        }
    }
    __syncthreads();
    if (tid < 64) g_score[d0 + tid] = sg[tid];
}

// ---------------- kernel 4: lo-limb fixup for |score| < THRESH columns ----------------
#define FX_LO 0
#define FX_WS 51200
#define FX_RED 52000
#define FX_LIST 53024
#define FX_CNT 54048
#define FX_TOTAL 54112

__global__ void __launch_bounds__(256)
st_fix(const float* __restrict__ pos_w,
       const float* __restrict__ time_w,
       const float* __restrict__ pol_w)
{
    extern __shared__ char fsm[];
    __nv_bfloat16* losm = (__nv_bfloat16*)(fsm + FX_LO);
    float* wsm = (float*)(fsm + FX_WS);
    float* red = (float*)(fsm + FX_RED);
    int* list = (int*)(fsm + FX_LIST);
    int* cnt = (int*)(fsm + FX_CNT);
    const int tid = threadIdx.x;
    const int k0 = blockIdx.x * 128;

    for (int idx = tid; idx < M_REAL * 16; idx += 256) {
        int m = idx >> 4, uu = idx & 15;
        *(uint4*)((char*)losm + m * 256 + uu * 16) =
            *(const uint4*)(g_Alo + (size_t)m * KK + k0 + uu * 8);
    }
    if (tid == 0) *cnt = 0;
    __syncthreads();

    for (int i = 0; i < NN / 256; i++) {
        int d = i * 256 + tid;
        if (fabsf(g_score[d]) < THRESH) {
            int p = atomicAdd(cnt, 1);
            list[p] = d;
        }
    }
    __syncthreads();
    const int nf = *cnt;

    for (int e = 0; e < nf; e++) {
        int d = list[e];
        if (tid < M_REAL)
            wsm[tid] = time_w[(size_t)(tid >> 1) * NN + d] * pol_w[(size_t)(tid & 1) * NN + d];
        __syncthreads();
        float part = 0.0f;
        if (tid < 128) {
            float p = pos_w[(size_t)(k0 + tid) * NN + d];
            float a0 = 0.0f, a1 = 0.0f;
            for (int m = 0; m < M_REAL; m += 2) {
                a0 += __bfloat162float(losm[m * 128 + tid]) * wsm[m];
                a1 += __bfloat162float(losm[(m + 1) * 128 + tid]) * wsm[m + 1];
            }
            part = p * (a0 + a1);
        }
        red[tid] = part;
        __syncthreads();
        for (int off = 128; off > 0; off >>= 1) {
            if (tid < off) red[tid] += red[tid + off];
            __syncthreads();
        }
        if (tid == 0) atomicAdd(&g_score[d], red[0]);
        __syncthreads();
    }
}

// ---------------- kernel 5: sign ----------------
__global__ void st_sign(float* __restrict__ out) {
    int i = blockIdx.x * blockDim.x + threadIdx.x;
    float v = g_score[i];
    out[i] = (v > 0.0f) ? 1.0f : ((v < 0.0f) ? -1.0f : 0.0f);
}

// ---------------- launch ----------------
extern "C" void kernel_launch(void* const* d_in, const int* in_sizes, int n_in,
                              void* d_out, int out_size) {
    const float* hist   = (const float*)d_in[0];   // [100, 2, 128, 128]
    const float* time_w = (const float*)d_in[1];   // [100, 8192]
    const float* pol_w  = (const float*)d_in[2];   // [2, 8192]
    const float* pos_w  = (const float*)d_in[3];   // [16384, 8192]
    float* out = (float*)d_out;                    // [8192]

    cudaFuncSetAttribute(st_gemm, cudaFuncAttributeMaxDynamicSharedMemorySize, SMEM_TOTAL);
    cudaFuncSetAttribute(convB2, cudaFuncAttributeMaxDynamicSharedMemorySize, CB_SMEM);
    cudaFuncSetAttribute(st_fix, cudaFuncAttributeMaxDynamicSharedMemorySize, FX_TOTAL);

    convA<<<(M_PAD * 2048) / 256, 256>>>(hist);
    convB2<<<NCH, 256, CB_SMEM>>>(pos_w);
    st_gemm<<<NDT, 256, SMEM_TOTAL>>>(time_w, pol_w);
    st_fix<<<KK / 128, 256, FX_TOTAL>>>(pos_w, time_w, pol_w);
    st_sign<<<NN / 256, 256>>>(out);
}

// round 13
// speedup vs baseline: 1.4637x; 1.4637x over previous
#include <cuda_runtime.h>
#include <cuda_bf16.h>
#include <cstdint>

// ---------------- Problem dims ----------------
#define M_REAL 200              // T*C rows
#define M_PAD 256               // padded to 16 m16 tiles (hi limb only)
#define KK 16384                // H*W
#define NN 8192                 // D
#define DTILE 64                // d columns per CTA
#define KCH 64                  // k per chunk
#define NCH (KK / KCH)          // 256 chunks
#define NDT (NN / DTILE)        // 128 CTAs
#define THRESH 8.0f
#define MAXFIX 1024

#define ABYTES (M_PAD * 128)    // 32768 per chunk (hi bf16, swizzled)
#define NSTAGE 4

// gemm smem layout
#define SM_BITS (NSTAGE * ABYTES)            // 131072: 2 x 512 bits buffers
#define SM_MBAR (SM_BITS + 1024)             // 132096
#define SM_SG (SM_MBAR + 32)                 // 132128
#define SMEM_TOTAL (SM_SG + 256)             // 132384

// ---------------- device scratch (static, no runtime allocation) ----------------
__device__ __nv_bfloat16 g_A[NCH * M_PAD * 64];   // 8 MB hi-limb, chunk-tiled+swizzled
__device__ __nv_bfloat16 g_Alo[M_REAL * KK];      // 6.5 MB lo-limb, flat
__device__ uint32_t g_Bbits[NCH * NDT * 128];     // 16 MB bit-packed pos_w signs
__device__ float g_score[NN];
__device__ float g_wfix[MAXFIX * 200];            // gathered weights for flagged cols
__device__ int g_list[MAXFIX];
__device__ int g_cnt;

// ---------------- PTX helpers ----------------
#define MBAR_INIT(a, c) asm volatile("mbarrier.init.shared.b64 [%0], %1;" :: "r"(a), "r"(c) : "memory")
#define MBAR_EXPECT(a, n) asm volatile("mbarrier.arrive.expect_tx.shared.b64 _, [%0], %1;" :: "r"(a), "r"(n) : "memory")

static __device__ __forceinline__ void mbar_wait(uint32_t mbar, uint32_t parity) {
    asm volatile(
        "{\n\t.reg .pred P1;\n\t"
        "WAIT_LOOP_%=:\n\t"
        "mbarrier.try_wait.parity.acquire.cta.shared::cta.b64 P1, [%0], %1, 0x989680;\n\t"
        "@P1 bra.uni WAIT_DONE_%=;\n\t"
        "bra.uni WAIT_LOOP_%=;\n\t"
        "WAIT_DONE_%=:\n\t}"
        :: "r"(mbar), "r"(parity) : "memory");
}

static __device__ __forceinline__ void bulk_g2s(uint32_t dst, const void* src,
                                                uint32_t bytes, uint32_t mbar) {
    asm volatile(
        "cp.async.bulk.shared::cluster.global.mbarrier::complete_tx::bytes [%0], [%1], %2, [%3];"
        :: "r"(dst), "l"(src), "r"(bytes), "r"(mbar) : "memory");
}

static __device__ __forceinline__ void ldsm_x4(uint32_t* r, uint32_t addr) {
    asm volatile("ldmatrix.sync.aligned.m8n8.x4.shared.b16 {%0,%1,%2,%3}, [%4];"
                 : "=r"(r[0]), "=r"(r[1]), "=r"(r[2]), "=r"(r[3]) : "r"(addr));
}
static __device__ __forceinline__ void mma_bf16(float* c, const uint32_t* a, const uint32_t* b) {
    asm volatile(
        "mma.sync.aligned.m16n8k16.row.col.f32.bf16.bf16.f32 "
        "{%0,%1,%2,%3}, {%4,%5,%6,%7}, {%8,%9}, {%0,%1,%2,%3};"
        : "+f"(c[0]), "+f"(c[1]), "+f"(c[2]), "+f"(c[3])
        : "r"(a[0]), "r"(a[1]), "r"(a[2]), "r"(a[3]), "r"(b[0]), "r"(b[1]));
}

// ---------------- kernel 1: hist -> hi bf16 (chunk-tiled, swizzled) + lo bf16 (flat) ----------------
__global__ void convA(const float* __restrict__ hist) {
    int idx = blockIdx.x * blockDim.x + threadIdx.x;   // 256 m x 2048 units
    if (idx == 0) g_cnt = 0;
    int m = idx >> 11;
    int u = idx & 2047;
    int kc = u >> 3, uu = u & 7;
    __nv_bfloat16 hi[8], lo[8];
    if (m < M_REAL) {
        const float* src = hist + (size_t)m * KK + u * 8;
        float4 f0 = *(const float4*)(src);
        float4 f1 = *(const float4*)(src + 4);
        float f[8] = {f0.x, f0.y, f0.z, f0.w, f1.x, f1.y, f1.z, f1.w};
        #pragma unroll
        for (int i = 0; i < 8; i++) {
            hi[i] = __float2bfloat16_rn(f[i]);
            lo[i] = __float2bfloat16_rn(f[i] - __bfloat162float(hi[i]));
        }
    } else {
        #pragma unroll
        for (int i = 0; i < 8; i++) hi[i] = __float2bfloat16_rn(0.f);
    }
    int sw = (uu ^ (m & 7)) * 16;
    *(uint4*)((char*)g_A + (size_t)kc * ABYTES + m * 128 + sw) = *(uint4*)hi;
    if (m < M_REAL)
        *(uint4*)(g_Alo + (size_t)m * KK + u * 8) = *(uint4*)lo;
}

// ---------------- kernel 2: pos_w -> bit-packed signs, (chunk,dtile)-tiled ----------------
#define CB_SMEM (64 * 257 * 4)   // 65792
__global__ void __launch_bounds__(256)
convB2(const float* __restrict__ pos_w) {
    extern __shared__ uint32_t bsm[];   // [64][257]
    const int tid = threadIdx.x;
    const int kc = blockIdx.x;

    for (int r = 0; r < 64; r++) {
        const float* src = pos_w + (size_t)(kc * 64 + r) * NN + tid * 32;
        uint32_t bits = 0;
        #pragma unroll
        for (int i = 0; i < 8; i++) {
            float4 f = *(const float4*)(src + i * 4);
            bits |= (__float_as_uint(f.x) >> 31) << (i * 4 + 0);
            bits |= (__float_as_uint(f.y) >> 31) << (i * 4 + 1);
            bits |= (__float_as_uint(f.z) >> 31) << (i * 4 + 2);
            bits |= (__float_as_uint(f.w) >> 31) << (i * 4 + 3);
        }
        bsm[r * 257 + tid] = bits;
    }
    __syncthreads();

    uint32_t* outp = g_Bbits + (size_t)kc * NDT * 128;
    #pragma unroll
    for (int it = 0; it < 64; it++) {
        int u = tid + it * 256;          // 0..16383
        int h = u & 1, k = (u >> 1) & 63, dt = u >> 7;
        outp[u] = bsm[k * 257 + dt * 2 + h];
    }
}

// ---------------- kernel 3: hi bf16 GEMM, fat-bulk A + register-expanded B ----------------
__global__ void __launch_bounds__(256)
st_gemm(const float* __restrict__ time_w,
        const float* __restrict__ pol_w,
        float* __restrict__ out)
{
    extern __shared__ char smem[];
    const uint32_t sbase = (uint32_t)__cvta_generic_to_shared(smem);
    const int tid = threadIdx.x;
    const int w = tid >> 5, lane = tid & 31;
    const int g = lane >> 2, t = lane & 3;
    const int wm = w & 3, wn = w >> 2;      // 4m x 2n warp grid
    const int dt = blockIdx.x;
    const int d0 = dt * DTILE;
    float* sg = (float*)(smem + SM_SG);
    uint32_t* bitsm = (uint32_t*)(smem + SM_BITS);

    if (tid < NSTAGE) MBAR_INIT(sbase + SM_MBAR + tid * 8, 1);
    if (tid < 64) sg[tid] = 0.0f;
    __syncthreads();

    // prologue: bits for chunks 0,1 (LDG); A bulks for stages 0..3
    if (tid < 64) {
        int cb = tid >> 5, l = tid & 31;
        uint4 v = *(const uint4*)(g_Bbits + ((size_t)cb * NDT + dt) * 128 + l * 4);
        *(uint4*)(bitsm + cb * 128 + l * 4) = v;
    }
    if (tid == 0) {
        #pragma unroll
        for (int s = 0; s < NSTAGE; s++) {
            uint32_t mb = sbase + SM_MBAR + s * 8;
            MBAR_EXPECT(mb, ABYTES);
            bulk_g2s(sbase + s * ABYTES, (const char*)g_A + (size_t)s * ABYTES, ABYTES, mb);
        }
    }
    __syncthreads();

    float acc[4][4][4];
    #pragma unroll
    for (int i = 0; i < 4; i++)
        #pragma unroll
        for (int j = 0; j < 4; j++)
            #pragma unroll
            for (int cc = 0; cc < 4; cc++) acc[i][j][cc] = 0.0f;

    const int arow_l = (lane & 7) + ((lane >> 3) & 1) * 8;
    const int asel = lane >> 4;

    for (int c = 0; c < NCH; c++) {
        const int s = c & 3;
        mbar_wait(sbase + SM_MBAR + s * 8, (uint32_t)((c >> 2) & 1));

        const uint32_t stA = sbase + (uint32_t)s * ABYTES;
        const uint32_t* bw = bitsm + (c & 1) * 128;
        #pragma unroll
        for (int kt = 0; kt < 4; kt++) {
            // build B fragments from sign bits (PTX spec layout: b0={B[2t][g],B[2t+1][g]}, b1=k+8)
            const int kbase = kt * 16 + 2 * t;
            uint32_t w0 = bw[(kbase) * 2 + wn];
            uint32_t w1 = bw[(kbase + 1) * 2 + wn];
            uint32_t w2 = bw[(kbase + 8) * 2 + wn];
            uint32_t w3 = bw[(kbase + 9) * 2 + wn];
            uint32_t bfr[4][2];
            #pragma unroll
            for (int j = 0; j < 4; j++) {
                int sh = j * 8 + g;
                bfr[j][0] = 0x3F803F80u | (((w0 >> sh) & 1u) << 15) | (((w1 >> sh) & 1u) << 31);
                bfr[j][1] = 0x3F803F80u | (((w2 >> sh) & 1u) << 15) | (((w3 >> sh) & 1u) << 31);
            }
            #pragma unroll
            for (int i = 0; i < 4; i++) {
                int r = (wm + 4 * i) * 16 + arow_l;
                int u = kt * 2 + asel;
                uint32_t a[4];
                ldsm_x4(a, stA + (uint32_t)(r * 128 + ((u ^ (r & 7)) << 4)));
                #pragma unroll
                for (int j = 0; j < 4; j++)
                    mma_bf16(acc[i][j], a, bfr[j]);
            }
        }
        __syncthreads();

        if (c + NSTAGE < NCH && tid == 0) {
            uint32_t mb = sbase + SM_MBAR + s * 8;
            MBAR_EXPECT(mb, ABYTES);
            bulk_g2s(sbase + s * ABYTES,
                     (const char*)g_A + (size_t)(c + NSTAGE) * ABYTES, ABYTES, mb);
        }
        if (c + 2 < NCH && tid < 32) {
            uint4 v = *(const uint4*)(g_Bbits + ((size_t)(c + 2) * NDT + dt) * 128 + tid * 4);
            *(uint4*)(bitsm + (c & 1) * 128 + tid * 4) = v;
        }
    }

    // ---- epilogue: score[d] = sum_m C[m,d]*time*pol; flag near-zero cols ----
    {
        float colsum[4][2];
        #pragma unroll
        for (int j = 0; j < 4; j++) { colsum[j][0] = 0.f; colsum[j][1] = 0.f; }
        #pragma unroll
        for (int i = 0; i < 4; i++) {
            int rg = (wm + 4 * i) * 16 + g;
            int m0 = rg, m1 = rg + 8;
            bool v0 = m0 < M_REAL, v1 = m1 < M_REAL;
            #pragma unroll
            for (int j = 0; j < 4; j++) {
                int d = d0 + (wn * 4 + j) * 8 + 2 * t;
                if (v0) {
                    float wa = time_w[(size_t)(m0 >> 1) * NN + d] * pol_w[(size_t)(m0 & 1) * NN + d];
                    float wb = time_w[(size_t)(m0 >> 1) * NN + d + 1] * pol_w[(size_t)(m0 & 1) * NN + d + 1];
                    colsum[j][0] += acc[i][j][0] * wa;
                    colsum[j][1] += acc[i][j][1] * wb;
                }
                if (v1) {
                    float wa = time_w[(size_t)(m1 >> 1) * NN + d] * pol_w[(size_t)(m1 & 1) * NN + d];
                    float wb = time_w[(size_t)(m1 >> 1) * NN + d + 1] * pol_w[(size_t)(m1 & 1) * NN + d + 1];
                    colsum[j][0] += acc[i][j][2] * wa;
                    colsum[j][1] += acc[i][j][3] * wb;
                }
            }
        }
        #pragma unroll
        for (int j = 0; j < 4; j++) {
            #pragma unroll
            for (int cx = 0; cx < 2; cx++) {
                float v = colsum[j][cx];
                v += __shfl_xor_sync(0xFFFFFFFFu, v, 4);
                v += __shfl_xor_sync(0xFFFFFFFFu, v, 8);
                v += __shfl_xor_sync(0xFFFFFFFFu, v, 16);
                if (g == 0)
                    atomicAdd(&sg[(wn * 4 + j) * 8 + 2 * t + cx], v);
            }
        }
    }
    __syncthreads();
    if (tid < 64) {
        int d = d0 + tid;
        float v = sg[tid];
        g_score[d] = v;
        if (fabsf(v) < THRESH) {
            int p = atomicAdd(&g_cnt, 1);
            if (p < MAXFIX)
                g_list[p] = d;
            else
                out[d] = (v > 0.0f) ? 1.0f : ((v < 0.0f) ? -1.0f : 0.0f);
        } else {
            out[d] = (v > 0.0f) ? 1.0f : ((v < 0.0f) ? -1.0f : 0.0f);
        }
    }
}

// ---------------- kernel 4: gather weights for flagged columns (once) ----------------
__global__ void wgather(const float* __restrict__ time_w,
                        const float* __restrict__ pol_w) {
    const int wid = threadIdx.x >> 5, lane = threadIdx.x & 31;
    int i = blockIdx.x * 8 + wid;
    int cnt = g_cnt; if (cnt > MAXFIX) cnt = MAXFIX;
    if (i >= cnt) return;
    int d = g_list[i];
    for (int m = lane; m < M_REAL; m += 32)
        g_wfix[i * 200 + m] =
            time_w[(size_t)(m >> 1) * NN + d] * pol_w[(size_t)(m & 1) * NN + d];
}

// ---------------- kernel 5: lo-limb fixup (k-slice CTAs, signs from bit tensor) ----------------
#define FXF_LO 0                      // 200 x 128 f32 = 102400
#define FXF_W 102400                  // 4 x 256 f32 = 4096
#define FX_TOTAL 106496

__global__ void __launch_bounds__(256)
st_fix() {
    extern __shared__ char fsm[];
    float* loF = (float*)(fsm + FXF_LO);
    float* w4 = (float*)(fsm + FXF_W);
    const int tid = threadIdx.x;
    const int k0 = blockIdx.x * 128;
    int cnt = g_cnt; if (cnt > MAXFIX) cnt = MAXFIX;
    if (cnt == 0) return;

    // load lo slice [200][128] as f32
    for (int idx = tid; idx < M_REAL * 16; idx += 256) {
        int m = idx >> 4, uu = idx & 15;
        uint4 v = *(const uint4*)(g_Alo + (size_t)m * KK + k0 + uu * 8);
        __nv_bfloat16* bp = (__nv_bfloat16*)&v;
        float* dst = loF + m * 128 + uu * 8;
        #pragma unroll
        for (int e = 0; e < 8; e++) dst[e] = __bfloat162float(bp[e]);
    }
    __syncthreads();

    const int cslot = tid >> 6, kp = tid & 63;
    const int kA = k0 + 2 * kp;
    const int kc = kA >> 6;

    for (int b0 = 0; b0 < cnt; b0 += 4) {
        // load weights for up to 4 columns
        for (int idx = tid; idx < 1024; idx += 256) {
            int cc = idx >> 8, m = idx & 255;
            if (m < M_REAL && b0 + cc < cnt)
                w4[cc * 256 + m] = g_wfix[(b0 + cc) * 200 + m];
        }
        __syncthreads();

        int i = b0 + cslot;
        bool valid = i < cnt;
        int d = valid ? g_list[i] : 0;
        // pos signs for (kA, d), (kA+1, d) from bit tensor
        const uint32_t* bwp = g_Bbits + ((size_t)kc * NDT + (d >> 6)) * 128;
        int h = (d & 63) >> 5, bit = d & 31;
        uint32_t wA = bwp[(kA & 63) * 2 + h];
        uint32_t wB = bwp[((kA + 1) & 63) * 2 + h];
        float s0 = ((wA >> bit) & 1u) ? -1.0f : 1.0f;
        float s1 = ((wB >> bit) & 1u) ? -1.0f : 1.0f;

        float a0 = 0.0f, a1 = 0.0f;
        const float* wv = w4 + cslot * 256;
        #pragma unroll 4
        for (int m = 0; m < M_REAL; m++) {
            float2 lv = *(float2*)(loF + m * 128 + 2 * kp);
            float ww = wv[m];
            a0 += lv.x * ww;
            a1 += lv.y * ww;
        }
        float part = valid ? (a0 * s0 + a1 * s1) : 0.0f;
        part += __shfl_xor_sync(0xFFFFFFFFu, part, 1);
        part += __shfl_xor_sync(0xFFFFFFFFu, part, 2);
        part += __shfl_xor_sync(0xFFFFFFFFu, part, 4);
        part += __shfl_xor_sync(0xFFFFFFFFu, part, 8);
        part += __shfl_xor_sync(0xFFFFFFFFu, part, 16);
        if ((tid & 31) == 0 && valid)
            atomicAdd(&g_score[d], part);
        __syncthreads();
    }
}

// ---------------- kernel 6: sign for flagged columns ----------------
__global__ void st_signfix(float* __restrict__ out) {
    int i = blockIdx.x * blockDim.x + threadIdx.x;
    int cnt = g_cnt; if (cnt > MAXFIX) cnt = MAXFIX;
    if (i < cnt) {
        int d = g_list[i];
        float v = g_score[d];
        out[d] = (v > 0.0f) ? 1.0f : ((v < 0.0f) ? -1.0f : 0.0f);
    }
}

// ---------------- launch ----------------
extern "C" void kernel_launch(void* const* d_in, const int* in_sizes, int n_in,
                              void* d_out, int out_size) {
    const float* hist   = (const float*)d_in[0];   // [100, 2, 128, 128]
    const float* time_w = (const float*)d_in[1];   // [100, 8192]
    const float* pol_w  = (const float*)d_in[2];   // [2, 8192]
    const float* pos_w  = (const float*)d_in[3];   // [16384, 8192]
    float* out = (float*)d_out;                    // [8192]

    cudaFuncSetAttribute(st_gemm, cudaFuncAttributeMaxDynamicSharedMemorySize, SMEM_TOTAL);
    cudaFuncSetAttribute(convB2, cudaFuncAttributeMaxDynamicSharedMemorySize, CB_SMEM);
    cudaFuncSetAttribute(st_fix, cudaFuncAttributeMaxDynamicSharedMemorySize, FX_TOTAL);

    convA<<<(M_PAD * 2048) / 256, 256>>>(hist);
    convB2<<<NCH, 256, CB_SMEM>>>(pos_w);
    st_gemm<<<NDT, 256, SMEM_TOTAL>>>(time_w, pol_w, out);
    wgather<<<MAXFIX / 8, 256>>>(time_w, pol_w);
    st_fix<<<KK / 128, 256, FX_TOTAL>>>();
    st_signfix<<<MAXFIX / 256, 256>>>(out);
}